// round 1
// baseline (speedup 1.0000x reference)
#include <cuda_runtime.h>
#include <math.h>
#include <float.h>

// Problem constants
constexpr int Bn   = 16;
constexpr int Sn   = 512;
constexpr int Dn   = 512;
constexpr int Hn   = 8;
constexpr int DKn  = 64;
constexpr int DFFn = 2048;
constexpr int BSn  = Bn * Sn;          // 8192 rows

// ---------------- scratch (static device globals; alloc-free) ----------------
__device__ float g_x  [Bn*Sn*Dn];
__device__ float g_y  [Bn*Sn*Dn];
__device__ float g_qk [Bn*Sn*Dn];
__device__ float g_v  [Bn*Sn*Dn];
__device__ float g_att[Bn*Sn*Dn];
__device__ float g_tmp[Bn*Sn*Dn];
__device__ float g_ffn[Bn*Sn*DFFn];
__device__ float g_sc [Bn*Hn*Sn*Sn];   // 128 MB score/attn buffer

// ---------------- reduction helpers ----------------
__device__ __forceinline__ float warp_sum(float v){
    #pragma unroll
    for (int o = 16; o > 0; o >>= 1) v += __shfl_xor_sync(0xffffffffu, v, o);
    return v;
}
__device__ __forceinline__ float warp_max(float v){
    #pragma unroll
    for (int o = 16; o > 0; o >>= 1) v = fmaxf(v, __shfl_xor_sync(0xffffffffu, v, o));
    return v;
}
__device__ __forceinline__ float block_sum(float v, float* red){
    int lane = threadIdx.x & 31, w = threadIdx.x >> 5, nw = blockDim.x >> 5;
    v = warp_sum(v);
    if (lane == 0) red[w] = v;
    __syncthreads();
    if (w == 0){
        float r = (lane < nw) ? red[lane] : 0.f;
        r = warp_sum(r);
        if (lane == 0) red[0] = r;
    }
    __syncthreads();
    float out = red[0];
    __syncthreads();
    return out;
}
__device__ __forceinline__ float block_max(float v, float* red){
    int lane = threadIdx.x & 31, w = threadIdx.x >> 5, nw = blockDim.x >> 5;
    v = warp_max(v);
    if (lane == 0) red[w] = v;
    __syncthreads();
    if (w == 0){
        float r = (lane < nw) ? red[lane] : -FLT_MAX;
        r = warp_max(r);
        if (lane == 0) red[0] = r;
    }
    __syncthreads();
    float out = red[0];
    __syncthreads();
    return out;
}

// ---------------- generic tiled SGEMM: C = A*B (+bias) (opt ReLU) ------------
// Row-major A[M,K] (lda), B[K,N] (ldb), C[M,N] (ldc). Batched via grid.z with
// (b,h) decomposition: off = zb*s?b + zh*s?h.
template<int BM,int BN,int BK,int TM,int TN,bool RELU>
__global__ __launch_bounds__((BM/TM)*(BN/TN))
void gemm_kernel(const float* __restrict__ A, const float* __restrict__ B,
                 const float* __restrict__ bias, float* __restrict__ C,
                 int M, int N, int K, int lda, int ldb, int ldc,
                 int Hdim, long sAb, long sAh, long sBb, long sBh,
                 long sCb, long sCh)
{
    constexpr int THREADS = (BM/TM)*(BN/TN);
    int z = blockIdx.z;
    int zb = z / Hdim, zh = z % Hdim;
    A += (long)zb*sAb + (long)zh*sAh;
    B += (long)zb*sBb + (long)zh*sBh;
    C += (long)zb*sCb + (long)zh*sCh;

    __shared__ float As[BK][BM+4];
    __shared__ float Bs[BK][BN+4];

    int tid  = threadIdx.x;
    int trow = tid / (BN/TN);
    int tcol = tid % (BN/TN);
    int row0 = blockIdx.y * BM;
    int col0 = blockIdx.x * BN;

    float acc[TM][TN];
    #pragma unroll
    for (int i = 0; i < TM; i++)
        #pragma unroll
        for (int j = 0; j < TN; j++) acc[i][j] = 0.f;

    for (int k0 = 0; k0 < K; k0 += BK){
        #pragma unroll
        for (int i = tid; i < BM*BK/4; i += THREADS){
            int idx = i*4; int r = idx / BK, c = idx % BK;
            float4 v = *(const float4*)(A + (long)(row0+r)*lda + k0 + c);
            As[c+0][r] = v.x; As[c+1][r] = v.y; As[c+2][r] = v.z; As[c+3][r] = v.w;
        }
        #pragma unroll
        for (int i = tid; i < BK*BN/4; i += THREADS){
            int idx = i*4; int r = idx / BN, c = idx % BN;
            *(float4*)&Bs[r][c] = *(const float4*)(B + (long)(k0+r)*ldb + col0 + c);
        }
        __syncthreads();
        #pragma unroll
        for (int kk = 0; kk < BK; kk++){
            float a[TM], bb[TN];
            #pragma unroll
            for (int i = 0; i < TM; i++) a[i] = As[kk][trow*TM + i];
            #pragma unroll
            for (int j = 0; j < TN; j++) bb[j] = Bs[kk][tcol*TN + j];
            #pragma unroll
            for (int i = 0; i < TM; i++)
                #pragma unroll
                for (int j = 0; j < TN; j++)
                    acc[i][j] = fmaf(a[i], bb[j], acc[i][j]);
        }
        __syncthreads();
    }

    #pragma unroll
    for (int i = 0; i < TM; i++){
        int r = row0 + trow*TM + i;
        #pragma unroll
        for (int j = 0; j < TN; j++){
            int cg = col0 + tcol*TN + j;
            float val = acc[i][j] + (bias ? bias[cg] : 0.f);
            if (RELU) val = fmaxf(val, 0.f);
            C[(long)r*ldc + cg] = val;
        }
    }
}

// ---------------- QK^T scores (scaled), causal tile-skip --------------------
// QK buffer layout [B,S,D]; head h uses cols [h*64, h*64+64). Writes
// scores[b,h,i,j] = (q_i . k_j)/8 for 64x64 tiles with j0 <= i0+63.
__global__ __launch_bounds__(256)
void qk_scores(const float* __restrict__ QK, float* __restrict__ sc)
{
    int j0 = blockIdx.x * 64, i0 = blockIdx.y * 64;
    if (j0 > i0 + 63) return;                 // fully masked tile (both mask types)
    int bh = blockIdx.z; int b = bh >> 3, h = bh & 7;
    const float* base = QK + (long)b*Sn*Dn + h*DKn;

    __shared__ float Qs[64][68];              // [d][row]
    __shared__ float Ks[64][68];
    int tid = threadIdx.x;
    #pragma unroll
    for (int t = tid; t < 1024; t += 256){
        int r = t >> 4, c4 = (t & 15) * 4;
        float4 q4 = *(const float4*)(base + (long)(i0+r)*Dn + c4);
        Qs[c4+0][r]=q4.x; Qs[c4+1][r]=q4.y; Qs[c4+2][r]=q4.z; Qs[c4+3][r]=q4.w;
        float4 k4 = *(const float4*)(base + (long)(j0+r)*Dn + c4);
        Ks[c4+0][r]=k4.x; Ks[c4+1][r]=k4.y; Ks[c4+2][r]=k4.z; Ks[c4+3][r]=k4.w;
    }
    __syncthreads();

    int ti = tid >> 4, tj = tid & 15;
    float c[4][4] = {};
    #pragma unroll
    for (int d = 0; d < 64; d++){
        float a[4], bv[4];
        #pragma unroll
        for (int u = 0; u < 4; u++){ a[u] = Qs[d][ti*4+u]; bv[u] = Ks[d][tj*4+u]; }
        #pragma unroll
        for (int u = 0; u < 4; u++)
            #pragma unroll
            for (int v = 0; v < 4; v++)
                c[u][v] = fmaf(a[u], bv[v], c[u][v]);
    }
    float* out = sc + (long)bh*Sn*Sn;
    #pragma unroll
    for (int u = 0; u < 4; u++){
        int i = i0 + ti*4 + u;
        #pragma unroll
        for (int v = 0; v < 4; v++)
            out[(long)i*Sn + j0 + tj*4 + v] = c[u][v] * 0.125f;
    }
}

// ---------------- fused mask/softmax/cumsum/decay/softmax/zero_pad ----------
// One block per (b,h,i) row. In-place on the score buffer.
__global__ __launch_bounds__(512)
void attn_row(float* __restrict__ sc, const float* __restrict__ gamma, int maskflag)
{
    int i = blockIdx.x, h = blockIdx.y, b = blockIdx.z;
    int j = threadIdx.x;
    float* row = sc + (((long)(b*Hn + h))*Sn + i)*Sn;

    __shared__ float sm[512];
    __shared__ float red[32];

    bool valid = maskflag ? (j <= i) : (j < i);
    float s = row[j];

    // softmax #1 (masked), then p = softmax * mask
    float m1   = block_max(valid ? s : -FLT_MAX, red);
    float e    = valid ? expf(s - m1) : 0.f;
    float sum1 = block_sum(e, red);
    float p    = (sum1 > 0.f) ? e / sum1 : 0.f;

    // inclusive cumsum (Hillis-Steele over 512)
    sm[j] = p; __syncthreads();
    #pragma unroll
    for (int off = 1; off < 512; off <<= 1){
        float v = sm[j];
        if (j >= off) v += sm[j - off];
        __syncthreads();
        sm[j] = v;
        __syncthreads();
    }
    float cum = sm[j];
    float tot = sm[511];
    __syncthreads();

    // distance decay
    float d2 = (tot - cum) * fabsf((float)i - (float)j);
    if (d2 < 0.f) d2 = 0.f;
    float dist = sqrtf(d2);
    float gm = gamma[h];
    float sp = (gm > 20.f) ? gm : log1pf(expf(gm));       // softplus
    float eff = expf(-sp * dist);
    eff = fminf(fmaxf(eff, 1e-5f), 1e5f);

    // softmax #2 on decayed scores
    float s2   = valid ? s * eff : -FLT_MAX;
    float m2   = block_max(s2, red);
    float e2   = valid ? expf(s2 - m2) : 0.f;
    float sum2 = block_sum(e2, red);
    float a    = (sum2 > 0.f) ? e2 / sum2 : 0.f;

    if (!maskflag && i == 0) a = 0.f;                     // zero_pad
    row[j] = a;
}

// ---------------- residual + LayerNorm (D = 512) ----------------------------
__global__ __launch_bounds__(256)
void add_ln(const float* __restrict__ base, const float* __restrict__ delta,
            const float* __restrict__ g, const float* __restrict__ bt,
            float* __restrict__ out)
{
    long row = blockIdx.x;
    const float* x  = base  + row*Dn;
    const float* dl = delta + row*Dn;
    int t = threadIdx.x;
    __shared__ float red[32];

    float v0 = x[t]       + dl[t];
    float v1 = x[t + 256] + dl[t + 256];
    float s  = block_sum(v0 + v1, red);
    float sq = block_sum(v0*v0 + v1*v1, red);
    float mu  = s * (1.f/Dn);
    float var = sq * (1.f/Dn) - mu*mu;
    float inv = rsqrtf(var + 1e-5f);
    out[row*Dn + t]       = (v0 - mu)*inv*g[t]       + bt[t];
    out[row*Dn + t + 256] = (v1 - mu)*inv*g[t + 256] + bt[t + 256];
}

// ---------------- host orchestration ----------------------------------------
static float* sym_addr(const void* s){
    void* p = nullptr;
    cudaGetSymbolAddress(&p, s);
    return (float*)p;
}

extern "C" void kernel_launch(void* const* d_in, const int* in_sizes, int n_in,
                              void* d_out, int out_size)
{
    (void)in_sizes; (void)n_in; (void)out_size;
    const float* q_embed  = (const float*)d_in[0];
    const float* qa_embed = (const float*)d_in[1];
    // d_in[2] (pid_embed) unused by emb_type='qid'
    const float* Wk    = (const float*)d_in[3];
    const float* bk    = (const float*)d_in[4];
    const float* Wv    = (const float*)d_in[5];
    const float* bv    = (const float*)d_in[6];
    const float* Wo    = (const float*)d_in[7];
    const float* bo    = (const float*)d_in[8];
    const float* gam   = (const float*)d_in[9];
    const float* ln1g  = (const float*)d_in[10];
    const float* ln1b  = (const float*)d_in[11];
    const float* W1    = (const float*)d_in[12];
    const float* b1    = (const float*)d_in[13];
    const float* W2    = (const float*)d_in[14];
    const float* b2    = (const float*)d_in[15];
    const float* ln2g  = (const float*)d_in[16];
    const float* ln2b  = (const float*)d_in[17];

    float* x   = sym_addr(g_x);
    float* y   = sym_addr(g_y);
    float* qk  = sym_addr(g_qk);
    float* v   = sym_addr(g_v);
    float* att = sym_addr(g_att);
    float* tmp = sym_addr(g_tmp);
    float* ffn = sym_addr(g_ffn);
    float* sc  = sym_addr(g_sc);

    const size_t embBytes = (size_t)Bn*Sn*Dn*sizeof(float);
    cudaMemcpyAsync(x, q_embed,  embBytes, cudaMemcpyDeviceToDevice, 0);
    cudaMemcpyAsync(y, qa_embed, embBytes, cudaMemcpyDeviceToDevice, 0);

    auto gemm = [&](const float* A, const float* Bm, const float* bias, float* C,
                    int M, int N, int K, bool relu){
        dim3 grid(N/128, M/128, 1);
        if (relu)
            gemm_kernel<128,128,16,8,8,true ><<<grid,256>>>(A,Bm,bias,C,M,N,K,K,N,N,
                                                            1,0,0,0,0,0,0);
        else
            gemm_kernel<128,128,16,8,8,false><<<grid,256>>>(A,Bm,bias,C,M,N,K,K,N,N,
                                                            1,0,0,0,0,0,0);
    };

    auto layer = [&](int l, float* q, const float* vals, int maskflag, bool pos){
        // kq_same: one projection serves both Q and K
        gemm(q,    Wk + (long)l*Dn*Dn, bk + (long)l*Dn, qk, BSn, Dn, Dn, false);
        gemm(vals, Wv + (long)l*Dn*Dn, bv + (long)l*Dn, v,  BSn, Dn, Dn, false);

        qk_scores<<<dim3(Sn/64, Sn/64, Bn*Hn), 256>>>(qk, sc);
        attn_row <<<dim3(Sn, Hn, Bn), 512>>>(sc, gam + (long)l*Hn, maskflag);

        // attn @ V  (batched over B*H; V/att are head-sliced views of [B,S,D])
        gemm_kernel<64,64,16,4,4,false><<<dim3(1, Sn/64, Bn*Hn), 256>>>(
            sc, v, nullptr, att, Sn, DKn, Sn,
            Sn, Dn, Dn,
            Hn, (long)Hn*Sn*Sn, (long)Sn*Sn,
                (long)Sn*Dn,    (long)DKn,
                (long)Sn*Dn,    (long)DKn);

        gemm(att, Wo + (long)l*Dn*Dn, bo + (long)l*Dn, tmp, BSn, Dn, Dn, false);
        add_ln<<<BSn,256>>>(q, tmp, ln1g + (long)l*Dn, ln1b + (long)l*Dn, q);

        if (pos){
            gemm(q,   W1 + (long)l*Dn*DFFn, b1 + (long)l*DFFn, ffn, BSn, DFFn, Dn, true);
            gemm(ffn, W2 + (long)l*DFFn*Dn, b2 + (long)l*Dn,   tmp, BSn, Dn, DFFn, false);
            add_ln<<<BSn,256>>>(q, tmp, ln2g + (long)l*Dn, ln2b + (long)l*Dn, q);
        }
    };

    // blocks_1: self-attn on y, mask=1, FFN
    layer(0, y, y, 1, true);
    layer(1, y, y, 1, true);
    // blocks_2: (mask=1, no FFN) then (mask=0, values=y, FFN)
    layer(2, x, x, 1, false);
    layer(3, x, y, 0, true);
    layer(4, x, x, 1, false);
    layer(5, x, y, 0, true);

    cudaMemcpyAsync(d_out, x, embBytes, cudaMemcpyDeviceToDevice, 0);
    cudaMemcpyAsync((char*)d_out + embBytes, y, embBytes, cudaMemcpyDeviceToDevice, 0);
}

// round 2
// speedup vs baseline: 1.3831x; 1.3831x over previous
#include <cuda_runtime.h>
#include <math.h>
#include <float.h>

// Problem constants
constexpr int Bn   = 16;
constexpr int Sn   = 512;
constexpr int Dn   = 512;
constexpr int Hn   = 8;
constexpr int DKn  = 64;
constexpr int DFFn = 2048;
constexpr int BSn  = Bn * Sn;          // 8192 rows

// ---------------- scratch (static device globals; alloc-free) ----------------
__device__ float g_x  [Bn*Sn*Dn];
__device__ float g_y  [Bn*Sn*Dn];
__device__ float g_qk [Bn*Sn*Dn];
__device__ float g_v  [Bn*Sn*Dn];
__device__ float g_att[Bn*Sn*Dn];
__device__ float g_tmp[Bn*Sn*Dn];
__device__ float g_ffn[Bn*Sn*DFFn];
__device__ float g_sc [Bn*Hn*Sn*Sn];   // 128 MB score/attn buffer

// ---------------- packed f32x2 helpers (Blackwell FFMA2; PTX-only) ----------
union F2u { unsigned long long u; float2 f; };

__device__ __forceinline__ void ffma2(unsigned long long &acc,
                                      unsigned long long a,
                                      unsigned long long b){
    asm("fma.rn.f32x2 %0, %1, %2, %0;" : "+l"(acc) : "l"(a), "l"(b));
}
__device__ __forceinline__ unsigned long long dup2(float x){
    unsigned long long r;
    asm("mov.b64 %0, {%1, %1};" : "=l"(r) : "f"(x));
    return r;
}

// ---------------- warp helpers ----------------
__device__ __forceinline__ float warp_sum(float v){
    #pragma unroll
    for (int o = 16; o > 0; o >>= 1) v += __shfl_xor_sync(0xffffffffu, v, o);
    return v;
}
__device__ __forceinline__ float warp_max(float v){
    #pragma unroll
    for (int o = 16; o > 0; o >>= 1) v = fmaxf(v, __shfl_xor_sync(0xffffffffu, v, o));
    return v;
}
__device__ __forceinline__ float block_sum(float v, float* red){
    int lane = threadIdx.x & 31, w = threadIdx.x >> 5, nw = blockDim.x >> 5;
    v = warp_sum(v);
    if (lane == 0) red[w] = v;
    __syncthreads();
    if (w == 0){
        float r = (lane < nw) ? red[lane] : 0.f;
        r = warp_sum(r);
        if (lane == 0) red[0] = r;
    }
    __syncthreads();
    float out = red[0];
    __syncthreads();
    return out;
}

// ---------------- generic tiled SGEMM: C = A*B (+bias) (opt ReLU) ------------
// Row-major A[M,K] (lda), B[K,N] (ldb), C[M,N] (ldc). Batched via grid.z.
// tri != 0 => A is (block-)lower-triangular in [M,K] space: K-loop capped at
// row0+BM (used for attn@V where attn[i,j]=0 for j>i).
template<int BM,int BN,int BK,int TM,int TN,bool RELU>
__global__ __launch_bounds__((BM/TM)*(BN/TN))
void gemm_kernel(const float* __restrict__ A, const float* __restrict__ B,
                 const float* __restrict__ bias, float* __restrict__ C,
                 int M, int N, int K, int lda, int ldb, int ldc,
                 int Hdim, long sAb, long sAh, long sBb, long sBh,
                 long sCb, long sCh, int tri)
{
    constexpr int THREADS = (BM/TM)*(BN/TN);
    int z = blockIdx.z;
    int zb = z / Hdim, zh = z % Hdim;
    A += (long)zb*sAb + (long)zh*sAh;
    B += (long)zb*sBb + (long)zh*sBh;
    C += (long)zb*sCb + (long)zh*sCh;

    __shared__ float As[BK][BM+4];
    __shared__ float Bs[BK][BN+4];

    int tid  = threadIdx.x;
    int trow = tid / (BN/TN);
    int tcol = tid % (BN/TN);
    int row0 = blockIdx.y * BM;
    int col0 = blockIdx.x * BN;

    F2u acc[TM][TN/2];
    #pragma unroll
    for (int i = 0; i < TM; i++)
        #pragma unroll
        for (int j = 0; j < TN/2; j++) acc[i][j].u = 0ull;

    int kEnd = tri ? min(K, row0 + BM) : K;

    for (int k0 = 0; k0 < kEnd; k0 += BK){
        #pragma unroll
        for (int i = tid; i < BM*BK/4; i += THREADS){
            int idx = i*4; int r = idx / BK, c = idx % BK;
            float4 v = *(const float4*)(A + (long)(row0+r)*lda + k0 + c);
            As[c+0][r] = v.x; As[c+1][r] = v.y; As[c+2][r] = v.z; As[c+3][r] = v.w;
        }
        #pragma unroll
        for (int i = tid; i < BK*BN/4; i += THREADS){
            int idx = i*4; int r = idx / BN, c = idx % BN;
            *(float4*)&Bs[r][c] = *(const float4*)(B + (long)(k0+r)*ldb + col0 + c);
        }
        __syncthreads();
        #pragma unroll
        for (int kk = 0; kk < BK; kk++){
            float a[TM];
            #pragma unroll
            for (int i = 0; i < TM; i += 4)
                *(float4*)&a[i] = *(const float4*)&As[kk][trow*TM + i];
            unsigned long long av[TM];
            #pragma unroll
            for (int i = 0; i < TM; i++) av[i] = dup2(a[i]);
            unsigned long long bv[TN/2];
            #pragma unroll
            for (int j = 0; j < TN/2; j++)
                bv[j] = *(const unsigned long long*)&Bs[kk][tcol*TN + 2*j];
            #pragma unroll
            for (int i = 0; i < TM; i++)
                #pragma unroll
                for (int j = 0; j < TN/2; j++)
                    ffma2(acc[i][j].u, av[i], bv[j]);
        }
        __syncthreads();
    }

    #pragma unroll
    for (int i = 0; i < TM; i++){
        int r = row0 + trow*TM + i;
        #pragma unroll
        for (int j = 0; j < TN/2; j++){
            int cg = col0 + tcol*TN + 2*j;
            float2 val = acc[i][j].f;
            if (bias){ val.x += bias[cg]; val.y += bias[cg+1]; }
            if (RELU){ val.x = fmaxf(val.x, 0.f); val.y = fmaxf(val.y, 0.f); }
            *(float2*)(C + (long)r*ldc + cg) = val;
        }
    }
}

// ---------------- QK^T scores (scaled), causal tile-skip --------------------
__global__ __launch_bounds__(256)
void qk_scores(const float* __restrict__ QK, float* __restrict__ sc)
{
    int j0 = blockIdx.x * 64, i0 = blockIdx.y * 64;
    if (j0 > i0 + 63) return;                 // fully masked tile
    int bh = blockIdx.z; int b = bh >> 3, h = bh & 7;
    const float* base = QK + (long)b*Sn*Dn + h*DKn;

    __shared__ float Qs[64][68];              // [d][row]
    __shared__ float Ks[64][68];
    int tid = threadIdx.x;
    #pragma unroll
    for (int t = tid; t < 1024; t += 256){
        int r = t >> 4, c4 = (t & 15) * 4;
        float4 q4 = *(const float4*)(base + (long)(i0+r)*Dn + c4);
        Qs[c4+0][r]=q4.x; Qs[c4+1][r]=q4.y; Qs[c4+2][r]=q4.z; Qs[c4+3][r]=q4.w;
        float4 k4 = *(const float4*)(base + (long)(j0+r)*Dn + c4);
        Ks[c4+0][r]=k4.x; Ks[c4+1][r]=k4.y; Ks[c4+2][r]=k4.z; Ks[c4+3][r]=k4.w;
    }
    __syncthreads();

    int ti = tid >> 4, tj = tid & 15;
    F2u c2[4][2];
    #pragma unroll
    for (int u = 0; u < 4; u++){ c2[u][0].u = 0ull; c2[u][1].u = 0ull; }
    #pragma unroll
    for (int d = 0; d < 64; d++){
        unsigned long long bv0 = *(const unsigned long long*)&Ks[d][tj*4];
        unsigned long long bv1 = *(const unsigned long long*)&Ks[d][tj*4+2];
        #pragma unroll
        for (int u = 0; u < 4; u++){
            unsigned long long av = dup2(Qs[d][ti*4+u]);
            ffma2(c2[u][0].u, av, bv0);
            ffma2(c2[u][1].u, av, bv1);
        }
    }
    float* out = sc + (long)bh*Sn*Sn;
    #pragma unroll
    for (int u = 0; u < 4; u++){
        int i = i0 + ti*4 + u;
        float2 v0 = c2[u][0].f, v1 = c2[u][1].f;
        v0.x *= 0.125f; v0.y *= 0.125f; v1.x *= 0.125f; v1.y *= 0.125f;
        *(float2*)(out + (long)i*Sn + j0 + tj*4)     = v0;
        *(float2*)(out + (long)i*Sn + j0 + tj*4 + 2) = v1;
    }
}

// ---------------- fused attention row pass: one WARP per row ---------------
// mask softmax -> cumsum -> distance decay -> softmax -> zero_pad, in-place.
// Row length 512 = 32 lanes x 16 contiguous elements. No smem, no barriers.
__global__ __launch_bounds__(256)
void attn_row(float* __restrict__ sc, const float* __restrict__ gamma, int maskflag)
{
    const unsigned FULL = 0xffffffffu;
    int warp = (blockIdx.x * blockDim.x + threadIdx.x) >> 5;
    int lane = threadIdx.x & 31;
    int i = warp & (Sn-1);
    int h = (warp >> 9) & (Hn-1);
    float* row = sc + (long)warp * Sn;
    int jbase = lane * 16;
    int lim = maskflag ? i : (i - 1);          // valid: j <= lim

    float s[16];
    #pragma unroll
    for (int q = 0; q < 4; q++)
        *(float4*)&s[q*4] = *(const float4*)(row + jbase + q*4);

    // ---- softmax #1 (masked) ----
    float m = -FLT_MAX;
    #pragma unroll
    for (int t = 0; t < 16; t++) if (jbase + t <= lim) m = fmaxf(m, s[t]);
    m = warp_max(m);

    float e[16]; float sum = 0.f;
    #pragma unroll
    for (int t = 0; t < 16; t++){
        e[t] = (jbase + t <= lim) ? __expf(s[t] - m) : 0.f;
        sum += e[t];
    }
    sum = warp_sum(sum);
    float inv1 = (sum > 0.f) ? 1.f / sum : 0.f;

    // ---- inclusive cumsum of e across the row ----
    float c[16]; float run = 0.f;
    #pragma unroll
    for (int t = 0; t < 16; t++){ run += e[t]; c[t] = run; }
    float incl = run;
    #pragma unroll
    for (int o = 1; o < 32; o <<= 1){
        float tsh = __shfl_up_sync(FULL, incl, o);
        if (lane >= o) incl += tsh;
    }
    float excl = incl - run;                   // exclusive prefix of this lane's chunk

    // ---- distance decay ----
    float gm = gamma[h];
    float sp = (gm > 20.f) ? gm : log1pf(__expf(gm));   // softplus
    float fi = (float)i;

    float s2[16];
    #pragma unroll
    for (int t = 0; t < 16; t++){
        float cumincl = excl + c[t];
        float rem = fmaxf(sum - cumincl, 0.f) * inv1;   // 1 - cumsum(p)
        float pos = fabsf(fi - (float)(jbase + t));
        float dist = sqrtf(rem * pos);
        float eff = __expf(-sp * dist);
        eff = fminf(fmaxf(eff, 1e-5f), 1e5f);
        s2[t] = s[t] * eff;
    }

    // ---- softmax #2 ----
    float m2 = -FLT_MAX;
    #pragma unroll
    for (int t = 0; t < 16; t++) if (jbase + t <= lim) m2 = fmaxf(m2, s2[t]);
    m2 = warp_max(m2);

    float a[16]; float sum2 = 0.f;
    #pragma unroll
    for (int t = 0; t < 16; t++){
        a[t] = (jbase + t <= lim) ? __expf(s2[t] - m2) : 0.f;
        sum2 += a[t];
    }
    sum2 = warp_sum(sum2);
    float inv2 = (sum2 > 0.f) ? 1.f / sum2 : 0.f;
    if (!maskflag && i == 0) inv2 = 0.f;       // zero_pad

    #pragma unroll
    for (int t = 0; t < 16; t++) a[t] *= inv2;
    #pragma unroll
    for (int q = 0; q < 4; q++)
        *(float4*)(row + jbase + q*4) = *(float4*)&a[q*4];
}

// ---------------- residual + LayerNorm (D = 512) ----------------------------
__global__ __launch_bounds__(256)
void add_ln(const float* __restrict__ base, const float* __restrict__ delta,
            const float* __restrict__ g, const float* __restrict__ bt,
            float* __restrict__ out)
{
    long row = blockIdx.x;
    const float* x  = base  + row*Dn;
    const float* dl = delta + row*Dn;
    int t = threadIdx.x;
    __shared__ float red[32];

    float v0 = x[t]       + dl[t];
    float v1 = x[t + 256] + dl[t + 256];
    float s  = block_sum(v0 + v1, red);
    float sq = block_sum(v0*v0 + v1*v1, red);
    float mu  = s * (1.f/Dn);
    float var = sq * (1.f/Dn) - mu*mu;
    float inv = rsqrtf(var + 1e-5f);
    out[row*Dn + t]       = (v0 - mu)*inv*g[t]       + bt[t];
    out[row*Dn + t + 256] = (v1 - mu)*inv*g[t + 256] + bt[t + 256];
}

// ---------------- host orchestration ----------------------------------------
static float* sym_addr(const void* s){
    void* p = nullptr;
    cudaGetSymbolAddress(&p, s);
    return (float*)p;
}

extern "C" void kernel_launch(void* const* d_in, const int* in_sizes, int n_in,
                              void* d_out, int out_size)
{
    (void)in_sizes; (void)n_in; (void)out_size;
    const float* q_embed  = (const float*)d_in[0];
    const float* qa_embed = (const float*)d_in[1];
    const float* Wk    = (const float*)d_in[3];
    const float* bk    = (const float*)d_in[4];
    const float* Wv    = (const float*)d_in[5];
    const float* bv    = (const float*)d_in[6];
    const float* Wo    = (const float*)d_in[7];
    const float* bo    = (const float*)d_in[8];
    const float* gam   = (const float*)d_in[9];
    const float* ln1g  = (const float*)d_in[10];
    const float* ln1b  = (const float*)d_in[11];
    const float* W1    = (const float*)d_in[12];
    const float* b1    = (const float*)d_in[13];
    const float* W2    = (const float*)d_in[14];
    const float* b2    = (const float*)d_in[15];
    const float* ln2g  = (const float*)d_in[16];
    const float* ln2b  = (const float*)d_in[17];

    float* x   = sym_addr(g_x);
    float* y   = sym_addr(g_y);
    float* qk  = sym_addr(g_qk);
    float* v   = sym_addr(g_v);
    float* att = sym_addr(g_att);
    float* tmp = sym_addr(g_tmp);
    float* ffn = sym_addr(g_ffn);
    float* sc  = sym_addr(g_sc);

    const size_t embBytes = (size_t)Bn*Sn*Dn*sizeof(float);
    cudaMemcpyAsync(x, q_embed,  embBytes, cudaMemcpyDeviceToDevice, 0);
    cudaMemcpyAsync(y, qa_embed, embBytes, cudaMemcpyDeviceToDevice, 0);

    auto gemm = [&](const float* A, const float* Bm, const float* bias, float* C,
                    int M, int N, int K, bool relu){
        dim3 grid(N/128, M/128, 1);
        if (relu)
            gemm_kernel<128,128,16,8,8,true ><<<grid,256>>>(A,Bm,bias,C,M,N,K,K,N,N,
                                                            1,0,0,0,0,0,0,0);
        else
            gemm_kernel<128,128,16,8,8,false><<<grid,256>>>(A,Bm,bias,C,M,N,K,K,N,N,
                                                            1,0,0,0,0,0,0,0);
    };

    auto layer = [&](int l, float* q, const float* vals, int maskflag, bool pos){
        // kq_same: one projection serves both Q and K
        gemm(q,    Wk + (long)l*Dn*Dn, bk + (long)l*Dn, qk, BSn, Dn, Dn, false);
        gemm(vals, Wv + (long)l*Dn*Dn, bv + (long)l*Dn, v,  BSn, Dn, Dn, false);

        qk_scores<<<dim3(Sn/64, Sn/64, Bn*Hn), 256>>>(qk, sc);
        attn_row <<<dim3(Bn*Hn*Sn/8, 1, 1), 256>>>(sc, gam + (long)l*Hn, maskflag);

        // attn @ V (batched over B*H; triangular K-cap since attn[i,j>i]=0)
        gemm_kernel<64,64,16,4,4,false><<<dim3(1, Sn/64, Bn*Hn), 256>>>(
            sc, v, nullptr, att, Sn, DKn, Sn,
            Sn, Dn, Dn,
            Hn, (long)Hn*Sn*Sn, (long)Sn*Sn,
                (long)Sn*Dn,    (long)DKn,
                (long)Sn*Dn,    (long)DKn, 1);

        gemm(att, Wo + (long)l*Dn*Dn, bo + (long)l*Dn, tmp, BSn, Dn, Dn, false);
        add_ln<<<BSn,256>>>(q, tmp, ln1g + (long)l*Dn, ln1b + (long)l*Dn, q);

        if (pos){
            gemm(q,   W1 + (long)l*Dn*DFFn, b1 + (long)l*DFFn, ffn, BSn, DFFn, Dn, true);
            gemm(ffn, W2 + (long)l*DFFn*Dn, b2 + (long)l*Dn,   tmp, BSn, Dn, DFFn, false);
            add_ln<<<BSn,256>>>(q, tmp, ln2g + (long)l*Dn, ln2b + (long)l*Dn, q);
        }
    };

    // blocks_1: self-attn on y, mask=1, FFN
    layer(0, y, y, 1, true);
    layer(1, y, y, 1, true);
    // blocks_2: (mask=1, no FFN) then (mask=0, values=y, FFN)
    layer(2, x, x, 1, false);
    layer(3, x, y, 0, true);
    layer(4, x, x, 1, false);
    layer(5, x, y, 0, true);

    cudaMemcpyAsync(d_out, x, embBytes, cudaMemcpyDeviceToDevice, 0);
    cudaMemcpyAsync((char*)d_out + embBytes, y, embBytes, cudaMemcpyDeviceToDevice, 0);
}

// round 6
// speedup vs baseline: 2.5626x; 1.8527x over previous
#include <cuda_runtime.h>
#include <cuda_bf16.h>
#include <math.h>
#include <float.h>
#include <stdint.h>

constexpr int Bn   = 16;
constexpr int Sn   = 512;
constexpr int Dn   = 512;
constexpr int Hn   = 8;
constexpr int DKn  = 64;
constexpr int DFFn = 2048;
constexpr int BSn  = Bn * Sn;          // 8192 rows
constexpr int Ln   = 6;

typedef __nv_bfloat16 bf16;

// ---------------- fp32 scratch ----------------
__device__ float g_x  [BSn*Dn];
__device__ float g_y  [BSn*Dn];
__device__ float g_qk [BSn*Dn];
__device__ float g_v  [BSn*Dn];
__device__ float g_att[BSn*Dn];
__device__ float g_tmp[BSn*Dn];
__device__ float g_sc [(size_t)Bn*Hn*Sn*Sn];   // 128 MB scores/attn

// ---------------- bf16 split scratch ----------------
__device__ __align__(128) bf16 g_xh[BSn*Dn],  g_xl[BSn*Dn];
__device__ __align__(128) bf16 g_yh[BSn*Dn],  g_yl[BSn*Dn];
__device__ __align__(128) bf16 g_ah[BSn*Dn],  g_al[BSn*Dn];
__device__ __align__(128) bf16 g_fh[BSn*DFFn],g_fl[BSn*DFFn];
// transposed split weights: [N,K] row-major
__device__ __align__(128) bf16 g_wkh[Ln*Dn*Dn],   g_wkl[Ln*Dn*Dn];
__device__ __align__(128) bf16 g_wvh[Ln*Dn*Dn],   g_wvl[Ln*Dn*Dn];
__device__ __align__(128) bf16 g_woh[Ln*Dn*Dn],   g_wol[Ln*Dn*Dn];
__device__ __align__(128) bf16 g_w1h[Ln*Dn*DFFn], g_w1l[Ln*Dn*DFFn];
__device__ __align__(128) bf16 g_w2h[Ln*DFFn*Dn], g_w2l[Ln*DFFn*Dn];

// ---------------- low-level helpers ----------------
__device__ __forceinline__ uint32_t smem_u32(const void* p){
    return (uint32_t)__cvta_generic_to_shared(p);
}
__device__ __forceinline__ void cp16(uint32_t dst, const void* src){
    asm volatile("cp.async.cg.shared.global [%0], [%1], 16;"
                 :: "r"(dst), "l"(src));
}
__device__ __forceinline__ void cp_commit(){
    asm volatile("cp.async.commit_group;" ::: "memory");
}
__device__ __forceinline__ void cp_wait0(){
    asm volatile("cp.async.wait_group 0;" ::: "memory");
}
__device__ __forceinline__ void ldm_x4(uint32_t* r, uint32_t addr){
    asm volatile("ldmatrix.sync.aligned.m8n8.x4.shared.b16 {%0,%1,%2,%3}, [%4];"
                 : "=r"(r[0]),"=r"(r[1]),"=r"(r[2]),"=r"(r[3]) : "r"(addr));
}
__device__ __forceinline__ void mma_bf16(float* c, const uint32_t* a,
                                         const uint32_t* b){
    asm volatile("mma.sync.aligned.m16n8k16.row.col.f32.bf16.bf16.f32 "
        "{%0,%1,%2,%3}, {%4,%5,%6,%7}, {%8,%9}, {%0,%1,%2,%3};"
        : "+f"(c[0]),"+f"(c[1]),"+f"(c[2]),"+f"(c[3])
        : "r"(a[0]),"r"(a[1]),"r"(a[2]),"r"(a[3]), "r"(b[0]),"r"(b[1]));
}

constexpr int HG_STAGE = 32768;              // A(16K)+B(16K) per stage
constexpr int HG_SMEM  = 2*HG_STAGE;         // 64 KB dynamic

// ---------------- HMMA split-bf16 GEMM --------------------------------------
// C[M,N] = A[M,K] @ B^T (B stored [N,K]) with A,B in (hi,lo) bf16 splits.
// 3 K-passes (Ah*Bh, Ah*Bl, Al*Bh) accumulate in register fp32.
// CTA: 128x128 tile, 256 thr (8 warps of 64x32). BK=64, XOR-swizzled smem,
// cp.async double buffering.
template<bool RELU, bool SPLIT, bool WF32>
__global__ void __launch_bounds__(256) hgemm(
    const bf16* __restrict__ Ah, const bf16* __restrict__ Al,
    const bf16* __restrict__ Bh, const bf16* __restrict__ Bl,
    const float* __restrict__ bias, float* __restrict__ C,
    bf16* __restrict__ Ch, bf16* __restrict__ Cl, int N, int K)
{
    extern __shared__ char smem[];
    uint32_t sb = smem_u32(smem);
    int tid = threadIdx.x, lane = tid & 31, wid = tid >> 5;
    int wm = (wid >> 2) * 64, wn = (wid & 3) * 32;
    int n0 = blockIdx.x * 128, m0 = blockIdx.y * 128;

    const int CH = K >> 6;
    const int T  = 3 * CH;

    float acc[4][4][4];
    #pragma unroll
    for (int i = 0; i < 4; i++)
        #pragma unroll
        for (int j = 0; j < 4; j++)
            #pragma unroll
            for (int q = 0; q < 4; q++) acc[i][j][q] = 0.f;

    auto preload = [&](int t){
        int p = t / CH, c = t % CH, k0 = c << 6;
        const bf16* Asrc = (p < 2)  ? Ah : Al;
        const bf16* Bsrc = (p == 1) ? Bl : Bh;
        uint32_t buf = sb + (t & 1) * HG_STAGE;
        #pragma unroll
        for (int g = tid; g < 1024; g += 256){
            int r = g >> 3, ch = g & 7;
            cp16(buf + (r << 7) + (((ch ^ (r & 7))) << 4),
                 Asrc + (size_t)(m0 + r) * K + k0 + ch * 8);
        }
        #pragma unroll
        for (int g = tid; g < 1024; g += 256){
            int r = g >> 3, ch = g & 7;
            cp16(buf + 16384 + (r << 7) + (((ch ^ (r & 7))) << 4),
                 Bsrc + (size_t)(n0 + r) * K + k0 + ch * 8);
        }
        cp_commit();
    };

    preload(0);
    for (int t = 0; t < T; t++){
        cp_wait0();
        __syncthreads();
        if (t + 1 < T) preload(t + 1);

        uint32_t abuf = sb + (t & 1) * HG_STAGE;
        uint32_t bbuf = abuf + 16384;
        #pragma unroll
        for (int kk = 0; kk < 4; kk++){
            uint32_t af[4][4];
            #pragma unroll
            for (int mt = 0; mt < 4; mt++){
                int m = wm + mt*16 + (lane & 7) + ((lane >> 3) & 1) * 8;
                int kc = kk*2 + (lane >> 4);
                ldm_x4(af[mt], abuf + (m << 7) + ((kc ^ (m & 7)) << 4));
            }
            uint32_t bfr[2][4];
            #pragma unroll
            for (int pr = 0; pr < 2; pr++){
                int n = wn + pr*16 + (lane & 7) + (lane >> 4) * 8;
                int kc = kk*2 + ((lane >> 3) & 1);
                ldm_x4(bfr[pr], bbuf + (n << 7) + ((kc ^ (n & 7)) << 4));
            }
            #pragma unroll
            for (int mt = 0; mt < 4; mt++)
                #pragma unroll
                for (int nt = 0; nt < 4; nt++)
                    mma_bf16(acc[mt][nt], af[mt], &bfr[nt >> 1][(nt & 1) * 2]);
        }
        __syncthreads();
    }

    // epilogue
    int qrow = lane >> 2, qcol = (lane & 3) * 2;
    #pragma unroll
    for (int mt = 0; mt < 4; mt++){
        #pragma unroll
        for (int nt = 0; nt < 4; nt++){
            int m = m0 + wm + mt*16 + qrow;
            int n = n0 + wn + nt*8 + qcol;
            float b0 = bias[n], b1 = bias[n+1];
            #pragma unroll
            for (int half = 0; half < 2; half++){
                int mm = m + half*8;
                float v0 = acc[mt][nt][half*2]   + b0;
                float v1 = acc[mt][nt][half*2+1] + b1;
                if (RELU){ v0 = fmaxf(v0, 0.f); v1 = fmaxf(v1, 0.f); }
                if (WF32){
                    float2 fv; fv.x = v0; fv.y = v1;
                    *(float2*)(C + (size_t)mm*N + n) = fv;
                }
                if (SPLIT){
                    bf16 h0 = __float2bfloat16(v0), h1 = __float2bfloat16(v1);
                    __nv_bfloat162 hp; hp.x = h0; hp.y = h1;
                    __nv_bfloat162 lp;
                    lp.x = __float2bfloat16(v0 - __bfloat162float(h0));
                    lp.y = __float2bfloat16(v1 - __bfloat162float(h1));
                    *(__nv_bfloat162*)(Ch + (size_t)mm*N + n) = hp;
                    *(__nv_bfloat162*)(Cl + (size_t)mm*N + n) = lp;
                }
            }
        }
    }
}

// ---------------- fp32 helpers (attn path) ----------------
union F2u { unsigned long long u; float2 f; };
__device__ __forceinline__ void ffma2(unsigned long long &acc,
                                      unsigned long long a, unsigned long long b){
    asm("fma.rn.f32x2 %0, %1, %2, %0;" : "+l"(acc) : "l"(a), "l"(b));
}
__device__ __forceinline__ unsigned long long dup2(float x){
    unsigned long long r;
    asm("mov.b64 %0, {%1, %1};" : "=l"(r) : "f"(x));
    return r;
}
__device__ __forceinline__ float warp_sum(float v){
    #pragma unroll
    for (int o = 16; o > 0; o >>= 1) v += __shfl_xor_sync(0xffffffffu, v, o);
    return v;
}
__device__ __forceinline__ float warp_max(float v){
    #pragma unroll
    for (int o = 16; o > 0; o >>= 1) v = fmaxf(v, __shfl_xor_sync(0xffffffffu, v, o));
    return v;
}
__device__ __forceinline__ float block_sum(float v, float* red){
    int lane = threadIdx.x & 31, w = threadIdx.x >> 5, nw = blockDim.x >> 5;
    v = warp_sum(v);
    if (lane == 0) red[w] = v;
    __syncthreads();
    if (w == 0){
        float r = (lane < nw) ? red[lane] : 0.f;
        r = warp_sum(r);
        if (lane == 0) red[0] = r;
    }
    __syncthreads();
    float out = red[0];
    __syncthreads();
    return out;
}

// fp32 batched GEMM for attn@V (per-head, triangular K-cap)
template<int BM,int BN,int BK,int TM,int TN>
__global__ __launch_bounds__((BM/TM)*(BN/TN))
void gemm_f32(const float* __restrict__ A, const float* __restrict__ B,
              float* __restrict__ C, int M, int N, int K,
              int lda, int ldb, int ldc,
              int Hdim, long sAb, long sAh, long sBb, long sBh,
              long sCb, long sCh)
{
    constexpr int THREADS = (BM/TM)*(BN/TN);
    int z = blockIdx.z;
    int zb = z / Hdim, zh = z % Hdim;
    A += (long)zb*sAb + (long)zh*sAh;
    B += (long)zb*sBb + (long)zh*sBh;
    C += (long)zb*sCb + (long)zh*sCh;

    __shared__ float As[BK][BM+4];
    __shared__ float Bs[BK][BN+4];
    int tid  = threadIdx.x;
    int trow = tid / (BN/TN);
    int tcol = tid % (BN/TN);
    int row0 = blockIdx.y * BM;
    int col0 = blockIdx.x * BN;

    F2u acc[TM][TN/2];
    #pragma unroll
    for (int i = 0; i < TM; i++)
        #pragma unroll
        for (int j = 0; j < TN/2; j++) acc[i][j].u = 0ull;

    int kEnd = min(K, row0 + BM);   // triangular cap
    for (int k0 = 0; k0 < kEnd; k0 += BK){
        #pragma unroll
        for (int i = tid; i < BM*BK/4; i += THREADS){
            int idx = i*4; int r = idx / BK, c = idx % BK;
            float4 v = *(const float4*)(A + (long)(row0+r)*lda + k0 + c);
            As[c+0][r]=v.x; As[c+1][r]=v.y; As[c+2][r]=v.z; As[c+3][r]=v.w;
        }
        #pragma unroll
        for (int i = tid; i < BK*BN/4; i += THREADS){
            int idx = i*4; int r = idx / BN, c = idx % BN;
            *(float4*)&Bs[r][c] = *(const float4*)(B + (long)(k0+r)*ldb + col0 + c);
        }
        __syncthreads();
        #pragma unroll
        for (int kk = 0; kk < BK; kk++){
            float a[TM];
            #pragma unroll
            for (int i = 0; i < TM; i++) a[i] = As[kk][trow*TM + i];
            unsigned long long av[TM];
            #pragma unroll
            for (int i = 0; i < TM; i++) av[i] = dup2(a[i]);
            unsigned long long bv[TN/2];
            #pragma unroll
            for (int j = 0; j < TN/2; j++)
                bv[j] = *(const unsigned long long*)&Bs[kk][tcol*TN + 2*j];
            #pragma unroll
            for (int i = 0; i < TM; i++)
                #pragma unroll
                for (int j = 0; j < TN/2; j++)
                    ffma2(acc[i][j].u, av[i], bv[j]);
        }
        __syncthreads();
    }
    #pragma unroll
    for (int i = 0; i < TM; i++){
        int r = row0 + trow*TM + i;
        #pragma unroll
        for (int j = 0; j < TN/2; j++){
            int cg = col0 + tcol*TN + 2*j;
            *(float2*)(C + (long)r*ldc + cg) = acc[i][j].f;
        }
    }
}

// ---------------- QK^T scores (scaled), causal tile-skip --------------------
__global__ __launch_bounds__(256)
void qk_scores(const float* __restrict__ QK, float* __restrict__ sc)
{
    int j0 = blockIdx.x * 64, i0 = blockIdx.y * 64;
    if (j0 > i0 + 63) return;
    int bh = blockIdx.z; int b = bh >> 3, h = bh & 7;
    const float* base = QK + (long)b*Sn*Dn + h*DKn;

    __shared__ float Qs[64][68];
    __shared__ float Ks[64][68];
    int tid = threadIdx.x;
    #pragma unroll
    for (int t = tid; t < 1024; t += 256){
        int r = t >> 4, c4 = (t & 15) * 4;
        float4 q4 = *(const float4*)(base + (long)(i0+r)*Dn + c4);
        Qs[c4+0][r]=q4.x; Qs[c4+1][r]=q4.y; Qs[c4+2][r]=q4.z; Qs[c4+3][r]=q4.w;
        float4 k4 = *(const float4*)(base + (long)(j0+r)*Dn + c4);
        Ks[c4+0][r]=k4.x; Ks[c4+1][r]=k4.y; Ks[c4+2][r]=k4.z; Ks[c4+3][r]=k4.w;
    }
    __syncthreads();

    int ti = tid >> 4, tj = tid & 15;
    F2u c2[4][2];
    #pragma unroll
    for (int u = 0; u < 4; u++){ c2[u][0].u = 0ull; c2[u][1].u = 0ull; }
    #pragma unroll
    for (int d = 0; d < 64; d++){
        unsigned long long bv0 = *(const unsigned long long*)&Ks[d][tj*4];
        unsigned long long bv1 = *(const unsigned long long*)&Ks[d][tj*4+2];
        #pragma unroll
        for (int u = 0; u < 4; u++){
            unsigned long long av = dup2(Qs[d][ti*4+u]);
            ffma2(c2[u][0].u, av, bv0);
            ffma2(c2[u][1].u, av, bv1);
        }
    }
    float* out = sc + (long)bh*Sn*Sn;
    #pragma unroll
    for (int u = 0; u < 4; u++){
        int i = i0 + ti*4 + u;
        float2 v0 = c2[u][0].f, v1 = c2[u][1].f;
        v0.x *= 0.125f; v0.y *= 0.125f; v1.x *= 0.125f; v1.y *= 0.125f;
        *(float2*)(out + (long)i*Sn + j0 + tj*4)     = v0;
        *(float2*)(out + (long)i*Sn + j0 + tj*4 + 2) = v1;
    }
}

// ---------------- fused attention row pass: one WARP per row ---------------
__global__ __launch_bounds__(256)
void attn_row(float* __restrict__ sc, const float* __restrict__ gamma, int maskflag)
{
    const unsigned FULL = 0xffffffffu;
    int warp = (blockIdx.x * blockDim.x + threadIdx.x) >> 5;
    int lane = threadIdx.x & 31;
    int i = warp & (Sn-1);
    int h = (warp >> 9) & (Hn-1);
    float* row = sc + (long)warp * Sn;
    int jbase = lane * 16;
    int lim = maskflag ? i : (i - 1);

    float s[16];
    #pragma unroll
    for (int q = 0; q < 4; q++)
        *(float4*)&s[q*4] = *(const float4*)(row + jbase + q*4);

    float m = -FLT_MAX;
    #pragma unroll
    for (int t = 0; t < 16; t++) if (jbase + t <= lim) m = fmaxf(m, s[t]);
    m = warp_max(m);

    float e[16]; float sum = 0.f;
    #pragma unroll
    for (int t = 0; t < 16; t++){
        e[t] = (jbase + t <= lim) ? __expf(s[t] - m) : 0.f;
        sum += e[t];
    }
    sum = warp_sum(sum);
    float inv1 = (sum > 0.f) ? 1.f / sum : 0.f;

    float c[16]; float run = 0.f;
    #pragma unroll
    for (int t = 0; t < 16; t++){ run += e[t]; c[t] = run; }
    float incl = run;
    #pragma unroll
    for (int o = 1; o < 32; o <<= 1){
        float tsh = __shfl_up_sync(FULL, incl, o);
        if (lane >= o) incl += tsh;
    }
    float excl = incl - run;

    float gm = gamma[h];
    float sp = (gm > 20.f) ? gm : log1pf(__expf(gm));
    float fi = (float)i;

    float s2[16];
    #pragma unroll
    for (int t = 0; t < 16; t++){
        float cumincl = excl + c[t];
        float rem = fmaxf(sum - cumincl, 0.f) * inv1;
        float pos = fabsf(fi - (float)(jbase + t));
        float dist = sqrtf(rem * pos);
        float eff = __expf(-sp * dist);
        eff = fminf(fmaxf(eff, 1e-5f), 1e5f);
        s2[t] = s[t] * eff;
    }

    float m2 = -FLT_MAX;
    #pragma unroll
    for (int t = 0; t < 16; t++) if (jbase + t <= lim) m2 = fmaxf(m2, s2[t]);
    m2 = warp_max(m2);

    float a[16]; float sum2 = 0.f;
    #pragma unroll
    for (int t = 0; t < 16; t++){
        a[t] = (jbase + t <= lim) ? __expf(s2[t] - m2) : 0.f;
        sum2 += a[t];
    }
    sum2 = warp_sum(sum2);
    float inv2 = (sum2 > 0.f) ? 1.f / sum2 : 0.f;
    if (!maskflag && i == 0) inv2 = 0.f;

    #pragma unroll
    for (int t = 0; t < 16; t++) a[t] *= inv2;
    #pragma unroll
    for (int q = 0; q < 4; q++)
        *(float4*)(row + jbase + q*4) = *(float4*)&a[q*4];
}

// ---------------- residual + LayerNorm (+ bf16 split out) -------------------
__global__ __launch_bounds__(256)
void add_ln(const float* __restrict__ base, const float* __restrict__ delta,
            const float* __restrict__ g, const float* __restrict__ bt,
            float* __restrict__ out, bf16* __restrict__ oh, bf16* __restrict__ ol)
{
    long row = blockIdx.x;
    const float* x  = base  + row*Dn;
    const float* dl = delta + row*Dn;
    int t = threadIdx.x;
    __shared__ float red[32];

    float v0 = x[t]       + dl[t];
    float v1 = x[t + 256] + dl[t + 256];
    float s  = block_sum(v0 + v1, red);
    float sq = block_sum(v0*v0 + v1*v1, red);
    float mu  = s * (1.f/Dn);
    float var = sq * (1.f/Dn) - mu*mu;
    float inv = rsqrtf(var + 1e-5f);
    float o0 = (v0 - mu)*inv*g[t]       + bt[t];
    float o1 = (v1 - mu)*inv*g[t + 256] + bt[t + 256];
    out[row*Dn + t]       = o0;
    out[row*Dn + t + 256] = o1;
    bf16 h0 = __float2bfloat16(o0), h1 = __float2bfloat16(o1);
    oh[row*Dn + t]       = h0;
    oh[row*Dn + t + 256] = h1;
    ol[row*Dn + t]       = __float2bfloat16(o0 - __bfloat162float(h0));
    ol[row*Dn + t + 256] = __float2bfloat16(o1 - __bfloat162float(h1));
}

// ---------------- fp32 -> bf16 split ----------------------------------------
__global__ __launch_bounds__(256)
void k_split(const float* __restrict__ x, bf16* __restrict__ h,
             bf16* __restrict__ l, int n4)
{
    int i = blockIdx.x * blockDim.x + threadIdx.x;
    if (i >= n4) return;
    float4 v = ((const float4*)x)[i];
    bf16 h0=__float2bfloat16(v.x), h1=__float2bfloat16(v.y);
    bf16 h2=__float2bfloat16(v.z), h3=__float2bfloat16(v.w);
    __nv_bfloat162 hp0; hp0.x=h0; hp0.y=h1;
    __nv_bfloat162 hp1; hp1.x=h2; hp1.y=h3;
    __nv_bfloat162 lp0, lp1;
    lp0.x=__float2bfloat16(v.x-__bfloat162float(h0));
    lp0.y=__float2bfloat16(v.y-__bfloat162float(h1));
    lp1.x=__float2bfloat16(v.z-__bfloat162float(h2));
    lp1.y=__float2bfloat16(v.w-__bfloat162float(h3));
    ((__nv_bfloat162*)h)[2*i]   = hp0;
    ((__nv_bfloat162*)h)[2*i+1] = hp1;
    ((__nv_bfloat162*)l)[2*i]   = lp0;
    ((__nv_bfloat162*)l)[2*i+1] = lp1;
}

// ---------------- fp32 W[K,N] -> split bf16 W^T[N,K] ------------------------
__global__ __launch_bounds__(256)
void k_splitT(const float* __restrict__ W, bf16* __restrict__ hT,
              bf16* __restrict__ lT, int K, int N)
{
    __shared__ float tile[32][33];
    int n0 = blockIdx.x * 32, k0 = blockIdx.y * 32;
    int tx = threadIdx.x & 31, ty = threadIdx.x >> 5;   // (32,8)
    #pragma unroll
    for (int i = 0; i < 32; i += 8)
        tile[ty+i][tx] = W[(size_t)(k0+ty+i)*N + n0+tx];
    __syncthreads();
    #pragma unroll
    for (int i = 0; i < 32; i += 8){
        float v = tile[tx][ty+i];                        // W[k0+tx][n0+ty+i]
        size_t o = (size_t)(n0+ty+i)*K + k0+tx;
        bf16 h = __float2bfloat16(v);
        hT[o] = h;
        lT[o] = __float2bfloat16(v - __bfloat162float(h));
    }
}

// ---------------- host orchestration ----------------------------------------
static float* sym_addr(const void* s){
    void* p = nullptr;
    cudaGetSymbolAddress(&p, s);
    return (float*)p;
}
static bf16* sym_addr_b(const void* s){
    void* p = nullptr;
    cudaGetSymbolAddress(&p, s);
    return (bf16*)p;
}

extern "C" void kernel_launch(void* const* d_in, const int* in_sizes, int n_in,
                              void* d_out, int out_size)
{
    (void)in_sizes; (void)n_in; (void)out_size;
    const float* q_embed  = (const float*)d_in[0];
    const float* qa_embed = (const float*)d_in[1];
    const float* Wk    = (const float*)d_in[3];
    const float* bk    = (const float*)d_in[4];
    const float* Wv    = (const float*)d_in[5];
    const float* bv    = (const float*)d_in[6];
    const float* Wo    = (const float*)d_in[7];
    const float* bo    = (const float*)d_in[8];
    const float* gam   = (const float*)d_in[9];
    const float* ln1g  = (const float*)d_in[10];
    const float* ln1b  = (const float*)d_in[11];
    const float* W1    = (const float*)d_in[12];
    const float* b1    = (const float*)d_in[13];
    const float* W2    = (const float*)d_in[14];
    const float* b2    = (const float*)d_in[15];
    const float* ln2g  = (const float*)d_in[16];
    const float* ln2b  = (const float*)d_in[17];

    float* x   = sym_addr(g_x);
    float* y   = sym_addr(g_y);
    float* qk  = sym_addr(g_qk);
    float* v   = sym_addr(g_v);
    float* att = sym_addr(g_att);
    float* tmp = sym_addr(g_tmp);
    float* sc  = sym_addr(g_sc);
    bf16 *xh=sym_addr_b(g_xh), *xl=sym_addr_b(g_xl);
    bf16 *yh=sym_addr_b(g_yh), *yl=sym_addr_b(g_yl);
    bf16 *ah=sym_addr_b(g_ah), *al=sym_addr_b(g_al);
    bf16 *fh=sym_addr_b(g_fh), *fl=sym_addr_b(g_fl);
    bf16 *wkh=sym_addr_b(g_wkh), *wkl=sym_addr_b(g_wkl);
    bf16 *wvh=sym_addr_b(g_wvh), *wvl=sym_addr_b(g_wvl);
    bf16 *woh=sym_addr_b(g_woh), *wol=sym_addr_b(g_wol);
    bf16 *w1h=sym_addr_b(g_w1h), *w1l=sym_addr_b(g_w1l);
    bf16 *w2h=sym_addr_b(g_w2h), *w2l=sym_addr_b(g_w2l);

    cudaFuncSetAttribute(hgemm<false,false,true>,
        cudaFuncAttributeMaxDynamicSharedMemorySize, HG_SMEM);
    cudaFuncSetAttribute(hgemm<true,true,false>,
        cudaFuncAttributeMaxDynamicSharedMemorySize, HG_SMEM);

    const size_t embBytes = (size_t)BSn*Dn*sizeof(float);
    cudaMemcpyAsync(x, q_embed,  embBytes, cudaMemcpyDeviceToDevice, 0);
    cudaMemcpyAsync(y, qa_embed, embBytes, cudaMemcpyDeviceToDevice, 0);

    // one-time weight transpose+split
    for (int l = 0; l < Ln; l++){
        long oD = (long)l*Dn*Dn, oF = (long)l*Dn*DFFn;
        k_splitT<<<dim3(Dn/32,  Dn/32 ), 256>>>(Wk+oD, wkh+oD, wkl+oD, Dn,   Dn);
        k_splitT<<<dim3(Dn/32,  Dn/32 ), 256>>>(Wv+oD, wvh+oD, wvl+oD, Dn,   Dn);
        k_splitT<<<dim3(Dn/32,  Dn/32 ), 256>>>(Wo+oD, woh+oD, wol+oD, Dn,   Dn);
        k_splitT<<<dim3(DFFn/32,Dn/32 ), 256>>>(W1+oF, w1h+oF, w1l+oF, Dn,   DFFn);
        k_splitT<<<dim3(Dn/32, DFFn/32), 256>>>(W2+oF, w2h+oF, w2l+oF, DFFn, Dn);
    }
    // initial activation splits
    k_split<<<(BSn*Dn/4+255)/256,256>>>(x, xh, xl, BSn*Dn/4);
    k_split<<<(BSn*Dn/4+255)/256,256>>>(y, yh, yl, BSn*Dn/4);

    auto tgM = [&](const bf16*Ah,const bf16*Al,const bf16*Bh,const bf16*Bl,
                   const float*bias, float*C, int N, int K){
        hgemm<false,false,true><<<dim3(N/128, BSn/128), 256, HG_SMEM>>>(
            Ah,Al,Bh,Bl,bias,C,nullptr,nullptr,N,K);
    };
    auto tgRelu = [&](const bf16*Ah,const bf16*Al,const bf16*Bh,const bf16*Bl,
                      const float*bias, bf16*Ch, bf16*Cl, int N, int K){
        hgemm<true,true,false><<<dim3(N/128, BSn/128), 256, HG_SMEM>>>(
            Ah,Al,Bh,Bl,bias,nullptr,Ch,Cl,N,K);
    };

    auto layer = [&](int l, float* q, bf16* qh, bf16* ql,
                     const bf16* vh, const bf16* vl, int maskflag, bool pos){
        long oD = (long)l*Dn*Dn, oF = (long)l*Dn*DFFn;
        // kq_same projection + V projection (tensor cores)
        tgM(qh, ql, wkh+oD, wkl+oD, bk + (long)l*Dn, qk, Dn, Dn);
        tgM(vh, vl, wvh+oD, wvl+oD, bv + (long)l*Dn, v,  Dn, Dn);

        qk_scores<<<dim3(Sn/64, Sn/64, Bn*Hn), 256>>>(qk, sc);
        attn_row <<<dim3(Bn*Hn*Sn/8, 1, 1), 256>>>(sc, gam + (long)l*Hn, maskflag);

        // attn @ V (fp32, triangular K-cap)
        gemm_f32<64,64,16,4,4><<<dim3(1, Sn/64, Bn*Hn), 256>>>(
            sc, v, att, Sn, DKn, Sn,
            Sn, Dn, Dn,
            Hn, (long)Hn*Sn*Sn, (long)Sn*Sn,
                (long)Sn*Dn,    (long)DKn,
                (long)Sn*Dn,    (long)DKn);

        k_split<<<(BSn*Dn/4+255)/256,256>>>(att, ah, al, BSn*Dn/4);
        tgM(ah, al, woh+oD, wol+oD, bo + (long)l*Dn, tmp, Dn, Dn);
        add_ln<<<BSn,256>>>(q, tmp, ln1g + (long)l*Dn, ln1b + (long)l*Dn, q, qh, ql);

        if (pos){
            tgRelu(qh, ql, w1h+oF, w1l+oF, b1 + (long)l*DFFn, fh, fl, DFFn, Dn);
            tgM(fh, fl, w2h+oF, w2l+oF, b2 + (long)l*Dn, tmp, Dn, DFFn);
            add_ln<<<BSn,256>>>(q, tmp, ln2g + (long)l*Dn, ln2b + (long)l*Dn, q, qh, ql);
        }
    };

    // blocks_1: self-attn on y, mask=1, FFN
    layer(0, y, yh, yl, yh, yl, 1, true);
    layer(1, y, yh, yl, yh, yl, 1, true);
    // blocks_2: (mask=1, no FFN) then (mask=0, values=y, FFN)
    layer(2, x, xh, xl, xh, xl, 1, false);
    layer(3, x, xh, xl, yh, yl, 0, true);
    layer(4, x, xh, xl, xh, xl, 1, false);
    layer(5, x, xh, xl, yh, yl, 0, true);

    cudaMemcpyAsync(d_out, x, embBytes, cudaMemcpyDeviceToDevice, 0);
    cudaMemcpyAsync((char*)d_out + embBytes, y, embBytes, cudaMemcpyDeviceToDevice, 0);
}

// round 7
// speedup vs baseline: 3.0787x; 1.2014x over previous
#include <cuda_runtime.h>
#include <cuda_bf16.h>
#include <math.h>
#include <float.h>
#include <stdint.h>

constexpr int Bn   = 16;
constexpr int Sn   = 512;
constexpr int Dn   = 512;
constexpr int Hn   = 8;
constexpr int DKn  = 64;
constexpr int DFFn = 2048;
constexpr int BSn  = Bn * Sn;          // 8192 rows
constexpr int Ln   = 6;

typedef __nv_bfloat16 bf16;

// ---------------- fp32 scratch ----------------
__device__ float g_x  [BSn*Dn];
__device__ float g_y  [BSn*Dn];
__device__ float g_tmp[BSn*Dn];
__device__ float g_sc [(size_t)Bn*Hn*Sn*Sn];   // 128 MB scores

// ---------------- bf16 split scratch ----------------
__device__ __align__(128) bf16 g_xh[BSn*Dn],  g_xl[BSn*Dn];
__device__ __align__(128) bf16 g_yh[BSn*Dn],  g_yl[BSn*Dn];
__device__ __align__(128) bf16 g_qkh[BSn*Dn], g_qkl[BSn*Dn];
__device__ __align__(128) bf16 g_vph[BSn*Dn], g_vpl[BSn*Dn];
__device__ __align__(128) bf16 g_ah[BSn*Dn],  g_al[BSn*Dn];
__device__ __align__(128) bf16 g_fh[BSn*DFFn],g_fl[BSn*DFFn];
__device__ __align__(128) bf16 g_ph[(size_t)Bn*Hn*Sn*Sn];   // 67 MB probs hi
__device__ __align__(128) bf16 g_pl[(size_t)Bn*Hn*Sn*Sn];   // 67 MB probs lo
// transposed split weights: [N,K] row-major
__device__ __align__(128) bf16 g_wkh[Ln*Dn*Dn],   g_wkl[Ln*Dn*Dn];
__device__ __align__(128) bf16 g_wvh[Ln*Dn*Dn],   g_wvl[Ln*Dn*Dn];
__device__ __align__(128) bf16 g_woh[Ln*Dn*Dn],   g_wol[Ln*Dn*Dn];
__device__ __align__(128) bf16 g_w1h[Ln*Dn*DFFn], g_w1l[Ln*Dn*DFFn];
__device__ __align__(128) bf16 g_w2h[Ln*DFFn*Dn], g_w2l[Ln*DFFn*Dn];

// ---------------- low-level helpers ----------------
__device__ __forceinline__ uint32_t smem_u32(const void* p){
    return (uint32_t)__cvta_generic_to_shared(p);
}
__device__ __forceinline__ void cp16(uint32_t dst, const void* src){
    asm volatile("cp.async.cg.shared.global [%0], [%1], 16;"
                 :: "r"(dst), "l"(src));
}
__device__ __forceinline__ void cp_commit(){
    asm volatile("cp.async.commit_group;" ::: "memory");
}
__device__ __forceinline__ void cp_wait0(){
    asm volatile("cp.async.wait_group 0;" ::: "memory");
}
__device__ __forceinline__ void ldm_x4(uint32_t* r, uint32_t addr){
    asm volatile("ldmatrix.sync.aligned.m8n8.x4.shared.b16 {%0,%1,%2,%3}, [%4];"
                 : "=r"(r[0]),"=r"(r[1]),"=r"(r[2]),"=r"(r[3]) : "r"(addr));
}
__device__ __forceinline__ void ldm_x4_t(uint32_t* r, uint32_t addr){
    asm volatile("ldmatrix.sync.aligned.m8n8.x4.trans.shared.b16 {%0,%1,%2,%3}, [%4];"
                 : "=r"(r[0]),"=r"(r[1]),"=r"(r[2]),"=r"(r[3]) : "r"(addr));
}
__device__ __forceinline__ void mma_bf16(float* c, const uint32_t* a,
                                         const uint32_t* b){
    asm volatile("mma.sync.aligned.m16n8k16.row.col.f32.bf16.bf16.f32 "
        "{%0,%1,%2,%3}, {%4,%5,%6,%7}, {%8,%9}, {%0,%1,%2,%3};"
        : "+f"(c[0]),"+f"(c[1]),"+f"(c[2]),"+f"(c[3])
        : "r"(a[0]),"r"(a[1]),"r"(a[2]),"r"(a[3]), "r"(b[0]),"r"(b[1]));
}
__device__ __forceinline__ void split2(float v0, float v1,
                                       __nv_bfloat162& hp, __nv_bfloat162& lp){
    bf16 h0 = __float2bfloat16(v0), h1 = __float2bfloat16(v1);
    hp.x = h0; hp.y = h1;
    lp.x = __float2bfloat16(v0 - __bfloat162float(h0));
    lp.y = __float2bfloat16(v1 - __bfloat162float(h1));
}

constexpr int HG_STAGE = 32768;              // A(16K)+B(16K) per stage
constexpr int HG_SMEM  = 2*HG_STAGE;         // 64 KB dynamic
constexpr int AV_STAGE = 24576;              // P(16K)+V(8K)
constexpr int AV_SMEM  = 2*AV_STAGE;         // 48 KB
constexpr int QK_SMEM  = 65536;              // Ah,Al,Bh,Bl 16K each

// ---------------- HMMA split-bf16 GEMM (dense projections/FFN) ---------------
// C[M,N] = A[M,K] @ B^T (B stored [N,K]); 3 passes Ah*Bh+Ah*Bl+Al*Bh.
template<bool RELU, bool SPLIT, bool WF32>
__global__ void __launch_bounds__(256) hgemm(
    const bf16* __restrict__ Ah, const bf16* __restrict__ Al,
    const bf16* __restrict__ Bh, const bf16* __restrict__ Bl,
    const float* __restrict__ bias, float* __restrict__ C,
    bf16* __restrict__ Ch, bf16* __restrict__ Cl, int N, int K)
{
    extern __shared__ char smem[];
    uint32_t sb = smem_u32(smem);
    int tid = threadIdx.x, lane = tid & 31, wid = tid >> 5;
    int wm = (wid >> 2) * 64, wn = (wid & 3) * 32;
    int n0 = blockIdx.x * 128, m0 = blockIdx.y * 128;

    const int CH = K >> 6;
    const int T  = 3 * CH;

    float acc[4][4][4];
    #pragma unroll
    for (int i = 0; i < 4; i++)
        #pragma unroll
        for (int j = 0; j < 4; j++)
            #pragma unroll
            for (int q = 0; q < 4; q++) acc[i][j][q] = 0.f;

    auto preload = [&](int t){
        int p = t / CH, c = t % CH, k0 = c << 6;
        const bf16* Asrc = (p < 2)  ? Ah : Al;
        const bf16* Bsrc = (p == 1) ? Bl : Bh;
        uint32_t buf = sb + (t & 1) * HG_STAGE;
        #pragma unroll
        for (int g = tid; g < 1024; g += 256){
            int r = g >> 3, ch = g & 7;
            cp16(buf + (r << 7) + ((ch ^ (r & 7)) << 4),
                 Asrc + (size_t)(m0 + r) * K + k0 + ch * 8);
        }
        #pragma unroll
        for (int g = tid; g < 1024; g += 256){
            int r = g >> 3, ch = g & 7;
            cp16(buf + 16384 + (r << 7) + ((ch ^ (r & 7)) << 4),
                 Bsrc + (size_t)(n0 + r) * K + k0 + ch * 8);
        }
        cp_commit();
    };

    preload(0);
    for (int t = 0; t < T; t++){
        cp_wait0();
        __syncthreads();
        if (t + 1 < T) preload(t + 1);

        uint32_t abuf = sb + (t & 1) * HG_STAGE;
        uint32_t bbuf = abuf + 16384;
        #pragma unroll
        for (int kk = 0; kk < 4; kk++){
            uint32_t af[4][4];
            #pragma unroll
            for (int mt = 0; mt < 4; mt++){
                int m = wm + mt*16 + (lane & 7) + ((lane >> 3) & 1) * 8;
                int kc = kk*2 + (lane >> 4);
                ldm_x4(af[mt], abuf + (m << 7) + ((kc ^ (m & 7)) << 4));
            }
            uint32_t bfr[2][4];
            #pragma unroll
            for (int pr = 0; pr < 2; pr++){
                int n = wn + pr*16 + (lane & 7) + (lane >> 4) * 8;
                int kc = kk*2 + ((lane >> 3) & 1);
                ldm_x4(bfr[pr], bbuf + (n << 7) + ((kc ^ (n & 7)) << 4));
            }
            #pragma unroll
            for (int mt = 0; mt < 4; mt++)
                #pragma unroll
                for (int nt = 0; nt < 4; nt++)
                    mma_bf16(acc[mt][nt], af[mt], &bfr[nt >> 1][(nt & 1) * 2]);
        }
        __syncthreads();
    }

    int qrow = lane >> 2, qcol = (lane & 3) * 2;
    #pragma unroll
    for (int mt = 0; mt < 4; mt++){
        #pragma unroll
        for (int nt = 0; nt < 4; nt++){
            int m = m0 + wm + mt*16 + qrow;
            int n = n0 + wn + nt*8 + qcol;
            float b0 = bias[n], b1 = bias[n+1];
            #pragma unroll
            for (int half = 0; half < 2; half++){
                int mm = m + half*8;
                float v0 = acc[mt][nt][half*2]   + b0;
                float v1 = acc[mt][nt][half*2+1] + b1;
                if (RELU){ v0 = fmaxf(v0, 0.f); v1 = fmaxf(v1, 0.f); }
                if (WF32){
                    float2 fv; fv.x = v0; fv.y = v1;
                    *(float2*)(C + (size_t)mm*N + n) = fv;
                }
                if (SPLIT){
                    __nv_bfloat162 hp, lp;
                    split2(v0, v1, hp, lp);
                    *(__nv_bfloat162*)(Ch + (size_t)mm*N + n) = hp;
                    *(__nv_bfloat162*)(Cl + (size_t)mm*N + n) = lp;
                }
            }
        }
    }
}

// ---------------- QK^T via HMMA: 128x128 tiles, K=64, triangular skip -------
__global__ void __launch_bounds__(256) qk_hmma(
    const bf16* __restrict__ qkh, const bf16* __restrict__ qkl,
    float* __restrict__ sc)
{
    int jt = blockIdx.x, it = blockIdx.y;
    if (jt > it) return;
    int bh = blockIdx.z, b = bh >> 3, h = bh & 7;
    int i0 = it * 128, j0 = jt * 128;

    extern __shared__ char smem[];
    uint32_t sb = smem_u32(smem);
    int tid = threadIdx.x, lane = tid & 31, wid = tid >> 5;

    const bf16* bh_ = qkh + (size_t)b*Sn*Dn + h*DKn;
    const bf16* bl_ = qkl + (size_t)b*Sn*Dn + h*DKn;
    for (int g = tid; g < 1024; g += 256){
        int r = g >> 3, ch = g & 7;
        uint32_t sw = (r << 7) + ((ch ^ (r & 7)) << 4);
        cp16(sb +         sw, bh_ + (size_t)(i0+r)*Dn + ch*8);
        cp16(sb + 16384 + sw, bl_ + (size_t)(i0+r)*Dn + ch*8);
        cp16(sb + 32768 + sw, bh_ + (size_t)(j0+r)*Dn + ch*8);
        cp16(sb + 49152 + sw, bl_ + (size_t)(j0+r)*Dn + ch*8);
    }
    cp_commit(); cp_wait0();
    __syncthreads();

    int wm = (wid >> 2) * 64, wn = (wid & 3) * 32;
    float acc[4][4][4];
    #pragma unroll
    for (int i = 0; i < 4; i++)
        #pragma unroll
        for (int j = 0; j < 4; j++)
            #pragma unroll
            for (int q = 0; q < 4; q++) acc[i][j][q] = 0.f;

    #pragma unroll
    for (int p = 0; p < 3; p++){
        uint32_t abuf = sb + ((p < 2) ? 0 : 16384);
        uint32_t bbuf = sb + 32768 + ((p == 1) ? 16384 : 0);
        #pragma unroll
        for (int kk = 0; kk < 4; kk++){
            uint32_t af[4][4];
            #pragma unroll
            for (int mt = 0; mt < 4; mt++){
                int m = wm + mt*16 + (lane & 7) + ((lane >> 3) & 1) * 8;
                int kc = kk*2 + (lane >> 4);
                ldm_x4(af[mt], abuf + (m << 7) + ((kc ^ (m & 7)) << 4));
            }
            uint32_t bfr[2][4];
            #pragma unroll
            for (int pr = 0; pr < 2; pr++){
                int n = wn + pr*16 + (lane & 7) + (lane >> 4) * 8;
                int kc = kk*2 + ((lane >> 3) & 1);
                ldm_x4(bfr[pr], bbuf + (n << 7) + ((kc ^ (n & 7)) << 4));
            }
            #pragma unroll
            for (int mt = 0; mt < 4; mt++)
                #pragma unroll
                for (int nt = 0; nt < 4; nt++)
                    mma_bf16(acc[mt][nt], af[mt], &bfr[nt >> 1][(nt & 1) * 2]);
        }
    }

    float* out = sc + (size_t)bh * Sn * Sn;
    int qrow = lane >> 2, qcol = (lane & 3) * 2;
    #pragma unroll
    for (int mt = 0; mt < 4; mt++)
        #pragma unroll
        for (int nt = 0; nt < 4; nt++)
            #pragma unroll
            for (int half = 0; half < 2; half++){
                int i = i0 + wm + mt*16 + qrow + half*8;
                int j = j0 + wn + nt*8 + qcol;
                float2 fv;
                fv.x = acc[mt][nt][half*2]   * 0.125f;
                fv.y = acc[mt][nt][half*2+1] * 0.125f;
                *(float2*)(out + (size_t)i*Sn + j) = fv;
            }
}

// ---------------- attn@V via HMMA (split probs x split V, trans-B) ----------
// Per CTA: 128 rows x 64 head-dims. K capped at (it+1)*128.
__global__ void __launch_bounds__(256) av_hmma(
    const bf16* __restrict__ ph, const bf16* __restrict__ pl,
    const bf16* __restrict__ vh, const bf16* __restrict__ vl,
    bf16* __restrict__ ah, bf16* __restrict__ al)
{
    int it = blockIdx.x, bh = blockIdx.y, b = bh >> 3, h = bh & 7;
    int i0 = it * 128;

    extern __shared__ char smem[];
    uint32_t sb = smem_u32(smem);
    int tid = threadIdx.x, lane = tid & 31, wid = tid >> 5;

    const bf16* Ph = ph + (size_t)bh * Sn * Sn;
    const bf16* Pl = pl + (size_t)bh * Sn * Sn;
    const bf16* Vh = vh + (size_t)b*Sn*Dn + h*DKn;
    const bf16* Vl = vl + (size_t)b*Sn*Dn + h*DKn;

    const int nch = (it + 1) * 2;   // 64-wide j chunks
    const int T = 3 * nch;

    float acc[2][4][4];
    #pragma unroll
    for (int i = 0; i < 2; i++)
        #pragma unroll
        for (int j = 0; j < 4; j++)
            #pragma unroll
            for (int q = 0; q < 4; q++) acc[i][j][q] = 0.f;

    auto preload = [&](int t){
        int p = t / nch, c = t % nch, j0 = c << 6;
        const bf16* Ps = (p < 2)  ? Ph : Pl;
        const bf16* Vs = (p == 1) ? Vl : Vh;
        uint32_t buf = sb + (t & 1) * AV_STAGE;
        #pragma unroll
        for (int g = tid; g < 1024; g += 256){
            int r = g >> 3, ch = g & 7;
            cp16(buf + (r << 7) + ((ch ^ (r & 7)) << 4),
                 Ps + (size_t)(i0 + r) * Sn + j0 + ch * 8);
        }
        #pragma unroll
        for (int g = tid; g < 512; g += 256){
            int r = g >> 3, ch = g & 7;
            cp16(buf + 16384 + (r << 7) + ((ch ^ (r & 7)) << 4),
                 Vs + (size_t)(j0 + r) * Dn + ch * 8);
        }
        cp_commit();
    };

    preload(0);
    int wm = (wid >> 1) * 32, wn = (wid & 1) * 32;
    for (int t = 0; t < T; t++){
        cp_wait0();
        __syncthreads();
        if (t + 1 < T) preload(t + 1);

        uint32_t pb = sb + (t & 1) * AV_STAGE;
        uint32_t vb = pb + 16384;
        #pragma unroll
        for (int kk = 0; kk < 4; kk++){
            uint32_t af[2][4];
            #pragma unroll
            for (int mt = 0; mt < 2; mt++){
                int m = wm + mt*16 + (lane & 7) + ((lane >> 3) & 1) * 8;
                int kc = kk*2 + (lane >> 4);
                ldm_x4(af[mt], pb + (m << 7) + ((kc ^ (m & 7)) << 4));
            }
            uint32_t bfr[2][4];
            #pragma unroll
            for (int ng = 0; ng < 2; ng++){
                int row  = kk*16 + (lane & 7) + ((lane >> 3) & 1) * 8;
                int ncol = wn + ng*16 + ((lane >> 4) & 1) * 8;
                ldm_x4_t(bfr[ng], vb + (row << 7) + (((ncol >> 3) ^ (row & 7)) << 4));
            }
            #pragma unroll
            for (int mt = 0; mt < 2; mt++)
                #pragma unroll
                for (int nt = 0; nt < 4; nt++)
                    mma_bf16(acc[mt][nt], af[mt], &bfr[nt >> 1][(nt & 1) * 2]);
        }
        __syncthreads();
    }

    int qrow = lane >> 2, qcol = (lane & 3) * 2;
    #pragma unroll
    for (int mt = 0; mt < 2; mt++)
        #pragma unroll
        for (int nt = 0; nt < 4; nt++)
            #pragma unroll
            for (int half = 0; half < 2; half++){
                int i = i0 + wm + mt*16 + qrow + half*8;
                int d = wn + nt*8 + qcol;
                size_t off = (size_t)(b*Sn + i) * Dn + h*DKn + d;
                __nv_bfloat162 hp, lp;
                split2(acc[mt][nt][half*2], acc[mt][nt][half*2+1], hp, lp);
                *(__nv_bfloat162*)(ah + off) = hp;
                *(__nv_bfloat162*)(al + off) = lp;
            }
}

// ---------------- warp helpers ----------------
__device__ __forceinline__ float warp_sum(float v){
    #pragma unroll
    for (int o = 16; o > 0; o >>= 1) v += __shfl_xor_sync(0xffffffffu, v, o);
    return v;
}
__device__ __forceinline__ float warp_max(float v){
    #pragma unroll
    for (int o = 16; o > 0; o >>= 1) v = fmaxf(v, __shfl_xor_sync(0xffffffffu, v, o));
    return v;
}
__device__ __forceinline__ float block_sum(float v, float* red){
    int lane = threadIdx.x & 31, w = threadIdx.x >> 5, nw = blockDim.x >> 5;
    v = warp_sum(v);
    if (lane == 0) red[w] = v;
    __syncthreads();
    if (w == 0){
        float r = (lane < nw) ? red[lane] : 0.f;
        r = warp_sum(r);
        if (lane == 0) red[0] = r;
    }
    __syncthreads();
    float out = red[0];
    __syncthreads();
    return out;
}

// ---------------- fused attention row pass (warp per row) -------------------
// reads fp32 scores, writes split-bf16 probs for j < ((i>>7)+1)*128 only.
__global__ __launch_bounds__(256)
void attn_row(const float* __restrict__ sc, bf16* __restrict__ ph,
              bf16* __restrict__ pl, const float* __restrict__ gamma,
              int maskflag)
{
    const unsigned FULL = 0xffffffffu;
    int warp = (blockIdx.x * blockDim.x + threadIdx.x) >> 5;
    int lane = threadIdx.x & 31;
    int i = warp & (Sn-1);
    int h = (warp >> 9) & (Hn-1);
    const float* row = sc + (size_t)warp * Sn;
    int jbase = lane * 16;
    int jlim = ((i >> 7) + 1) << 7;
    bool act = jbase < jlim;
    int lim = maskflag ? i : (i - 1);

    float s[16];
    if (act){
        #pragma unroll
        for (int q = 0; q < 4; q++)
            *(float4*)&s[q*4] = *(const float4*)(row + jbase + q*4);
    } else {
        #pragma unroll
        for (int t = 0; t < 16; t++) s[t] = 0.f;
    }

    float m = -FLT_MAX;
    #pragma unroll
    for (int t = 0; t < 16; t++) if (jbase + t <= lim) m = fmaxf(m, s[t]);
    m = warp_max(m);

    float e[16]; float sum = 0.f;
    #pragma unroll
    for (int t = 0; t < 16; t++){
        e[t] = (jbase + t <= lim) ? __expf(s[t] - m) : 0.f;
        sum += e[t];
    }
    sum = warp_sum(sum);
    float inv1 = (sum > 0.f) ? 1.f / sum : 0.f;

    float c[16]; float run = 0.f;
    #pragma unroll
    for (int t = 0; t < 16; t++){ run += e[t]; c[t] = run; }
    float incl = run;
    #pragma unroll
    for (int o = 1; o < 32; o <<= 1){
        float tsh = __shfl_up_sync(FULL, incl, o);
        if (lane >= o) incl += tsh;
    }
    float excl = incl - run;

    float gm = gamma[h];
    float sp = (gm > 20.f) ? gm : log1pf(__expf(gm));
    float fi = (float)i;

    float s2[16];
    #pragma unroll
    for (int t = 0; t < 16; t++){
        float cumincl = excl + c[t];
        float rem = fmaxf(sum - cumincl, 0.f) * inv1;
        float pos = fabsf(fi - (float)(jbase + t));
        float dist = sqrtf(rem * pos);
        float eff = __expf(-sp * dist);
        eff = fminf(fmaxf(eff, 1e-5f), 1e5f);
        s2[t] = s[t] * eff;
    }

    float m2 = -FLT_MAX;
    #pragma unroll
    for (int t = 0; t < 16; t++) if (jbase + t <= lim) m2 = fmaxf(m2, s2[t]);
    m2 = warp_max(m2);

    float a[16]; float sum2 = 0.f;
    #pragma unroll
    for (int t = 0; t < 16; t++){
        a[t] = (jbase + t <= lim) ? __expf(s2[t] - m2) : 0.f;
        sum2 += a[t];
    }
    sum2 = warp_sum(sum2);
    float inv2 = (sum2 > 0.f) ? 1.f / sum2 : 0.f;
    if (!maskflag && i == 0) inv2 = 0.f;

    if (act){
        __nv_bfloat162 hp[8], lp[8];
        #pragma unroll
        for (int t = 0; t < 8; t++)
            split2(a[2*t] * inv2, a[2*t+1] * inv2, hp[t], lp[t]);
        bf16* pr = ph + (size_t)warp * Sn + jbase;
        bf16* lr = pl + (size_t)warp * Sn + jbase;
        *(uint4*)pr       = *(uint4*)&hp[0];
        *(uint4*)(pr + 8) = *(uint4*)&hp[4];
        *(uint4*)lr       = *(uint4*)&lp[0];
        *(uint4*)(lr + 8) = *(uint4*)&lp[4];
    }
}

// ---------------- residual + LayerNorm (+ bf16 split out) -------------------
__global__ __launch_bounds__(256)
void add_ln(const float* __restrict__ base, const float* __restrict__ delta,
            const float* __restrict__ g, const float* __restrict__ bt,
            float* __restrict__ out, bf16* __restrict__ oh, bf16* __restrict__ ol)
{
    long row = blockIdx.x;
    const float* x  = base  + row*Dn;
    const float* dl = delta + row*Dn;
    int t = threadIdx.x;
    __shared__ float red[32];

    float v0 = x[t]       + dl[t];
    float v1 = x[t + 256] + dl[t + 256];
    float s  = block_sum(v0 + v1, red);
    float sq = block_sum(v0*v0 + v1*v1, red);
    float mu  = s * (1.f/Dn);
    float var = sq * (1.f/Dn) - mu*mu;
    float inv = rsqrtf(var + 1e-5f);
    float o0 = (v0 - mu)*inv*g[t]       + bt[t];
    float o1 = (v1 - mu)*inv*g[t + 256] + bt[t + 256];
    out[row*Dn + t]       = o0;
    out[row*Dn + t + 256] = o1;
    bf16 h0 = __float2bfloat16(o0), h1 = __float2bfloat16(o1);
    oh[row*Dn + t]       = h0;
    oh[row*Dn + t + 256] = h1;
    ol[row*Dn + t]       = __float2bfloat16(o0 - __bfloat162float(h0));
    ol[row*Dn + t + 256] = __float2bfloat16(o1 - __bfloat162float(h1));
}

// ---------------- fp32 -> bf16 split ----------------------------------------
__global__ __launch_bounds__(256)
void k_split(const float* __restrict__ x, bf16* __restrict__ h,
             bf16* __restrict__ l, int n4)
{
    int i = blockIdx.x * blockDim.x + threadIdx.x;
    if (i >= n4) return;
    float4 v = ((const float4*)x)[i];
    __nv_bfloat162 hp0, hp1, lp0, lp1;
    split2(v.x, v.y, hp0, lp0);
    split2(v.z, v.w, hp1, lp1);
    ((__nv_bfloat162*)h)[2*i]   = hp0;
    ((__nv_bfloat162*)h)[2*i+1] = hp1;
    ((__nv_bfloat162*)l)[2*i]   = lp0;
    ((__nv_bfloat162*)l)[2*i+1] = lp1;
}

// ---------------- fp32 W[K,N] -> split bf16 W^T[N,K] ------------------------
__global__ __launch_bounds__(256)
void k_splitT(const float* __restrict__ W, bf16* __restrict__ hT,
              bf16* __restrict__ lT, int K, int N)
{
    __shared__ float tile[32][33];
    int n0 = blockIdx.x * 32, k0 = blockIdx.y * 32;
    int tx = threadIdx.x & 31, ty = threadIdx.x >> 5;   // (32,8)
    #pragma unroll
    for (int i = 0; i < 32; i += 8)
        tile[ty+i][tx] = W[(size_t)(k0+ty+i)*N + n0+tx];
    __syncthreads();
    #pragma unroll
    for (int i = 0; i < 32; i += 8){
        float v = tile[tx][ty+i];
        size_t o = (size_t)(n0+ty+i)*K + k0+tx;
        bf16 h = __float2bfloat16(v);
        hT[o] = h;
        lT[o] = __float2bfloat16(v - __bfloat162float(h));
    }
}

// ---------------- host orchestration ----------------------------------------
static float* sym_addr(const void* s){
    void* p = nullptr;
    cudaGetSymbolAddress(&p, s);
    return (float*)p;
}
static bf16* sym_addr_b(const void* s){
    void* p = nullptr;
    cudaGetSymbolAddress(&p, s);
    return (bf16*)p;
}

extern "C" void kernel_launch(void* const* d_in, const int* in_sizes, int n_in,
                              void* d_out, int out_size)
{
    (void)in_sizes; (void)n_in; (void)out_size;
    const float* q_embed  = (const float*)d_in[0];
    const float* qa_embed = (const float*)d_in[1];
    const float* Wk    = (const float*)d_in[3];
    const float* bk    = (const float*)d_in[4];
    const float* Wv    = (const float*)d_in[5];
    const float* bv    = (const float*)d_in[6];
    const float* Wo    = (const float*)d_in[7];
    const float* bo    = (const float*)d_in[8];
    const float* gam   = (const float*)d_in[9];
    const float* ln1g  = (const float*)d_in[10];
    const float* ln1b  = (const float*)d_in[11];
    const float* W1    = (const float*)d_in[12];
    const float* b1    = (const float*)d_in[13];
    const float* W2    = (const float*)d_in[14];
    const float* b2    = (const float*)d_in[15];
    const float* ln2g  = (const float*)d_in[16];
    const float* ln2b  = (const float*)d_in[17];

    float* x   = sym_addr(g_x);
    float* y   = sym_addr(g_y);
    float* tmp = sym_addr(g_tmp);
    float* sc  = sym_addr(g_sc);
    bf16 *xh=sym_addr_b(g_xh), *xl=sym_addr_b(g_xl);
    bf16 *yh=sym_addr_b(g_yh), *yl=sym_addr_b(g_yl);
    bf16 *qkh=sym_addr_b(g_qkh), *qkl=sym_addr_b(g_qkl);
    bf16 *vph=sym_addr_b(g_vph), *vpl=sym_addr_b(g_vpl);
    bf16 *ah=sym_addr_b(g_ah), *al=sym_addr_b(g_al);
    bf16 *fh=sym_addr_b(g_fh), *fl=sym_addr_b(g_fl);
    bf16 *ph=sym_addr_b(g_ph), *pl=sym_addr_b(g_pl);
    bf16 *wkh=sym_addr_b(g_wkh), *wkl=sym_addr_b(g_wkl);
    bf16 *wvh=sym_addr_b(g_wvh), *wvl=sym_addr_b(g_wvl);
    bf16 *woh=sym_addr_b(g_woh), *wol=sym_addr_b(g_wol);
    bf16 *w1h=sym_addr_b(g_w1h), *w1l=sym_addr_b(g_w1l);
    bf16 *w2h=sym_addr_b(g_w2h), *w2l=sym_addr_b(g_w2l);

    cudaFuncSetAttribute(hgemm<false,false,true>,
        cudaFuncAttributeMaxDynamicSharedMemorySize, HG_SMEM);
    cudaFuncSetAttribute(hgemm<true,true,false>,
        cudaFuncAttributeMaxDynamicSharedMemorySize, HG_SMEM);
    cudaFuncSetAttribute(hgemm<false,true,false>,
        cudaFuncAttributeMaxDynamicSharedMemorySize, HG_SMEM);
    cudaFuncSetAttribute(qk_hmma,
        cudaFuncAttributeMaxDynamicSharedMemorySize, QK_SMEM);
    cudaFuncSetAttribute(av_hmma,
        cudaFuncAttributeMaxDynamicSharedMemorySize, AV_SMEM);

    const size_t embBytes = (size_t)BSn*Dn*sizeof(float);
    cudaMemcpyAsync(x, q_embed,  embBytes, cudaMemcpyDeviceToDevice, 0);
    cudaMemcpyAsync(y, qa_embed, embBytes, cudaMemcpyDeviceToDevice, 0);

    // one-time weight transpose+split
    for (int l = 0; l < Ln; l++){
        long oD = (long)l*Dn*Dn, oF = (long)l*Dn*DFFn;
        k_splitT<<<dim3(Dn/32,  Dn/32 ), 256>>>(Wk+oD, wkh+oD, wkl+oD, Dn,   Dn);
        k_splitT<<<dim3(Dn/32,  Dn/32 ), 256>>>(Wv+oD, wvh+oD, wvl+oD, Dn,   Dn);
        k_splitT<<<dim3(Dn/32,  Dn/32 ), 256>>>(Wo+oD, woh+oD, wol+oD, Dn,   Dn);
        k_splitT<<<dim3(DFFn/32,Dn/32 ), 256>>>(W1+oF, w1h+oF, w1l+oF, Dn,   DFFn);
        k_splitT<<<dim3(Dn/32, DFFn/32), 256>>>(W2+oF, w2h+oF, w2l+oF, DFFn, Dn);
    }
    k_split<<<(BSn*Dn/4+255)/256,256>>>(x, xh, xl, BSn*Dn/4);
    k_split<<<(BSn*Dn/4+255)/256,256>>>(y, yh, yl, BSn*Dn/4);

    auto tgM = [&](const bf16*Ah,const bf16*Al,const bf16*Bh,const bf16*Bl,
                   const float*bias, float*C, int N, int K){
        hgemm<false,false,true><<<dim3(N/128, BSn/128), 256, HG_SMEM>>>(
            Ah,Al,Bh,Bl,bias,C,nullptr,nullptr,N,K);
    };
    auto tgSplit = [&](const bf16*Ah,const bf16*Al,const bf16*Bh,const bf16*Bl,
                       const float*bias, bf16*Ch, bf16*Cl, int N, int K){
        hgemm<false,true,false><<<dim3(N/128, BSn/128), 256, HG_SMEM>>>(
            Ah,Al,Bh,Bl,bias,nullptr,Ch,Cl,N,K);
    };
    auto tgRelu = [&](const bf16*Ah,const bf16*Al,const bf16*Bh,const bf16*Bl,
                      const float*bias, bf16*Ch, bf16*Cl, int N, int K){
        hgemm<true,true,false><<<dim3(N/128, BSn/128), 256, HG_SMEM>>>(
            Ah,Al,Bh,Bl,bias,nullptr,Ch,Cl,N,K);
    };

    auto layer = [&](int l, float* q, bf16* qh, bf16* ql,
                     const bf16* vsh, const bf16* vsl, int maskflag, bool pos){
        long oD = (long)l*Dn*Dn, oF = (long)l*Dn*DFFn;
        // kq_same projection + V projection -> split bf16 outputs
        tgSplit(qh,  ql,  wkh+oD, wkl+oD, bk + (long)l*Dn, qkh, qkl, Dn, Dn);
        tgSplit(vsh, vsl, wvh+oD, wvl+oD, bv + (long)l*Dn, vph, vpl, Dn, Dn);

        qk_hmma<<<dim3(4, 4, Bn*Hn), 256, QK_SMEM>>>(qkh, qkl, sc);
        attn_row<<<dim3(Bn*Hn*Sn/8, 1, 1), 256>>>(sc, ph, pl,
                                                  gam + (long)l*Hn, maskflag);
        av_hmma<<<dim3(4, Bn*Hn), 256, AV_SMEM>>>(ph, pl, vph, vpl, ah, al);

        tgM(ah, al, woh+oD, wol+oD, bo + (long)l*Dn, tmp, Dn, Dn);
        add_ln<<<BSn,256>>>(q, tmp, ln1g + (long)l*Dn, ln1b + (long)l*Dn, q, qh, ql);

        if (pos){
            tgRelu(qh, ql, w1h+oF, w1l+oF, b1 + (long)l*DFFn, fh, fl, DFFn, Dn);
            tgM(fh, fl, w2h+oF, w2l+oF, b2 + (long)l*Dn, tmp, Dn, DFFn);
            add_ln<<<BSn,256>>>(q, tmp, ln2g + (long)l*Dn, ln2b + (long)l*Dn, q, qh, ql);
        }
    };

    // blocks_1: self-attn on y, mask=1, FFN
    layer(0, y, yh, yl, yh, yl, 1, true);
    layer(1, y, yh, yl, yh, yl, 1, true);
    // blocks_2: (mask=1, no FFN) then (mask=0, values=y, FFN)
    layer(2, x, xh, xl, xh, xl, 1, false);
    layer(3, x, xh, xl, yh, yl, 0, true);
    layer(4, x, xh, xl, xh, xl, 1, false);
    layer(5, x, xh, xl, yh, yl, 0, true);

    cudaMemcpyAsync(d_out, x, embBytes, cudaMemcpyDeviceToDevice, 0);
    cudaMemcpyAsync((char*)d_out + embBytes, y, embBytes, cudaMemcpyDeviceToDevice, 0);
}